// round 14
// baseline (speedup 1.0000x reference)
#include <cuda_runtime.h>
#include <math.h>

#define BATCH   2048
#define FID     65536
#define ROWS    4                   // rows per block (full columns)
#define NBLK    (BATCH / ROWS)      // 512 blocks
#define THREADS 256
#define NIT     (FID / (THREADS * 4))  // 64 column iterations

// Scratch (zero-initialized; counter self-resets each run for graph replay)
__device__ float        g_lossp[NBLK];
__device__ unsigned int g_final_count;

// ---------------------------------------------------------------------------
// R10 body with deeper unroll: 16 independent LDG.128 per scheduling window
// (unroll 4), register budget raised via min-blocks 3. Probes whether more
// per-warp loads in flight lifts DRAM busy% past the 83% plateau.
// out layout: [logits(2048), pred(2048), loss(1)]
// ---------------------------------------------------------------------------
__global__ void __launch_bounds__(THREADS, 3) lr_kernel(
    const float* __restrict__ gate, const float* __restrict__ bias,
    const float* __restrict__ global_bias, const float* __restrict__ label,
    float* __restrict__ out)
{
    const int b    = blockIdx.x;
    const int tid  = threadIdx.x;
    const int warp = tid >> 5;
    const int lane = tid & 31;
    const size_t row0 = (size_t)b * ROWS;

    float s0 = 0.0f, s1 = 0.0f, s2 = 0.0f, s3 = 0.0f;

    const float* g0 = gate + row0 * FID;

#pragma unroll 4
    for (int it = 0; it < NIT; ++it) {
        const int col = it * (THREADS * 4) + tid * 4;
        const float4 bb = *reinterpret_cast<const float4*>(bias + col);
        float4 x0 = *reinterpret_cast<const float4*>(g0 + col);
        float4 x1 = *reinterpret_cast<const float4*>(g0 + FID + col);
        float4 x2 = *reinterpret_cast<const float4*>(g0 + 2 * FID + col);
        float4 x3 = *reinterpret_cast<const float4*>(g0 + 3 * FID + col);
        s0 += x0.x * bb.x + x0.y * bb.y + x0.z * bb.z + x0.w * bb.w;
        s1 += x1.x * bb.x + x1.y * bb.y + x1.z * bb.z + x1.w * bb.w;
        s2 += x2.x * bb.x + x2.y * bb.y + x2.z * bb.z + x2.w * bb.w;
        s3 += x3.x * bb.x + x3.y * bb.y + x3.z * bb.z + x3.w * bb.w;
    }

    // Block reduction: warp shfl per row-sum, then 8 warp values per row.
    float s[4] = {s0, s1, s2, s3};
    __shared__ float sm[ROWS][8];
#pragma unroll
    for (int r = 0; r < ROWS; ++r) {
        float v = s[r];
        v += __shfl_xor_sync(0xffffffffu, v, 16);
        v += __shfl_xor_sync(0xffffffffu, v, 8);
        v += __shfl_xor_sync(0xffffffffu, v, 4);
        v += __shfl_xor_sync(0xffffffffu, v, 2);
        v += __shfl_xor_sync(0xffffffffu, v, 1);
        if (lane == 0) sm[r][warp] = v;
    }
    __syncthreads();

    // Threads 0..3 finalize one row each: logit, pred, per-row loss.
    __shared__ float sloss[ROWS];
    if (tid < ROWS) {
        float t = 0.0f;
#pragma unroll
        for (int w = 0; w < 8; ++w) t += sm[tid][w];   // fixed order
        const int row = (int)row0 + tid;
        float logit = t + global_bias[0];
        out[row]         = logit;
        out[BATCH + row] = 1.0f / (1.0f + __expf(-logit));
        float y = label[row];
        sloss[tid] = fmaxf(logit, 0.0f) - logit * y + log1pf(expf(-fabsf(logit)));
    }
    __syncthreads();

    // Per-block loss -> global; last block reduces (deterministic order).
    __shared__ int s_is_last;
    if (tid == 0) {
        g_lossp[b] = (sloss[0] + sloss[1]) + (sloss[2] + sloss[3]);
        __threadfence();
        unsigned old = atomicAdd(&g_final_count, 1u);
        s_is_last = (old == NBLK - 1);
        if (s_is_last) g_final_count = 0;   // reset for next graph replay
    }
    __syncthreads();
    if (!s_is_last) return;

    __threadfence();
    __shared__ float sl[THREADS];
    sl[tid] = g_lossp[tid] + g_lossp[tid + THREADS];
    __syncthreads();
#pragma unroll
    for (int off = THREADS / 2; off > 0; off >>= 1) {
        if (tid < off) sl[tid] += sl[tid + off];
        __syncthreads();
    }
    if (tid == 0) out[2 * BATCH] = sl[0];
}

// ---------------------------------------------------------------------------
extern "C" void kernel_launch(void* const* d_in, const int* in_sizes, int n_in,
                              void* d_out, int out_size)
{
    const float* gate        = (const float*)d_in[0]; // [2048, 65536]
    const float* sparse_bias = (const float*)d_in[1]; // [65536]
    const float* global_bias = (const float*)d_in[2]; // [1]
    const float* label       = (const float*)d_in[3]; // [2048]
    float* out = (float*)d_out;                       // [4097]

    lr_kernel<<<NBLK, THREADS>>>(gate, sparse_bias, global_bias, label, out);
}

// round 15
// speedup vs baseline: 1.1716x; 1.1716x over previous
#include <cuda_runtime.h>
#include <math.h>

#define BATCH   2048
#define FID     65536
#define ROWS    4                   // rows per block (full columns)
#define NBLK    (BATCH / ROWS)      // 512 blocks
#define THREADS 256
#define NIT     (FID / (THREADS * 4))  // 64 column iterations

// Scratch (zero-initialized; counter self-resets each run for graph replay)
__device__ float        g_lossp[NBLK];
__device__ unsigned int g_final_count;

// ---------------------------------------------------------------------------
// Converged kernel (R10/R13, measured 81.9us / ~83% DRAM): each block owns 4
// complete rows (1 MB of gate) and emits logits/pred directly — no partials,
// no second launch. 4 independent LDG.128 per iteration at unroll 2 / regs 56
// / occ 4 blocks is the measured optimum of the MLP-vs-occupancy curve
// (R11: fewer loads -> 98.8us; R14: more loads -> 94.2us). Loss via per-block
// fence+atomic; last block reduces 512 values in fixed order (deterministic).
// out layout: [logits(2048), pred(2048), loss(1)]
// ---------------------------------------------------------------------------
__global__ void __launch_bounds__(THREADS, 4) lr_kernel(
    const float* __restrict__ gate, const float* __restrict__ bias,
    const float* __restrict__ global_bias, const float* __restrict__ label,
    float* __restrict__ out)
{
    const int b    = blockIdx.x;
    const int tid  = threadIdx.x;
    const int warp = tid >> 5;
    const int lane = tid & 31;
    const size_t row0 = (size_t)b * ROWS;

    float s0 = 0.0f, s1 = 0.0f, s2 = 0.0f, s3 = 0.0f;

    const float* g0 = gate + row0 * FID;

#pragma unroll 2
    for (int it = 0; it < NIT; ++it) {
        const int col = it * (THREADS * 4) + tid * 4;
        const float4 bb = *reinterpret_cast<const float4*>(bias + col);
        float4 x0 = *reinterpret_cast<const float4*>(g0 + col);
        float4 x1 = *reinterpret_cast<const float4*>(g0 + FID + col);
        float4 x2 = *reinterpret_cast<const float4*>(g0 + 2 * FID + col);
        float4 x3 = *reinterpret_cast<const float4*>(g0 + 3 * FID + col);
        s0 += x0.x * bb.x + x0.y * bb.y + x0.z * bb.z + x0.w * bb.w;
        s1 += x1.x * bb.x + x1.y * bb.y + x1.z * bb.z + x1.w * bb.w;
        s2 += x2.x * bb.x + x2.y * bb.y + x2.z * bb.z + x2.w * bb.w;
        s3 += x3.x * bb.x + x3.y * bb.y + x3.z * bb.z + x3.w * bb.w;
    }

    // Block reduction: warp shfl per row-sum, then 8 warp values per row.
    float s[4] = {s0, s1, s2, s3};
    __shared__ float sm[ROWS][8];
#pragma unroll
    for (int r = 0; r < ROWS; ++r) {
        float v = s[r];
        v += __shfl_xor_sync(0xffffffffu, v, 16);
        v += __shfl_xor_sync(0xffffffffu, v, 8);
        v += __shfl_xor_sync(0xffffffffu, v, 4);
        v += __shfl_xor_sync(0xffffffffu, v, 2);
        v += __shfl_xor_sync(0xffffffffu, v, 1);
        if (lane == 0) sm[r][warp] = v;
    }
    __syncthreads();

    // Threads 0..3 finalize one row each: logit, pred, per-row loss.
    __shared__ float sloss[ROWS];
    if (tid < ROWS) {
        float t = 0.0f;
#pragma unroll
        for (int w = 0; w < 8; ++w) t += sm[tid][w];   // fixed order
        const int row = (int)row0 + tid;
        float logit = t + global_bias[0];
        out[row]         = logit;
        out[BATCH + row] = 1.0f / (1.0f + __expf(-logit));
        float y = label[row];
        sloss[tid] = fmaxf(logit, 0.0f) - logit * y + log1pf(expf(-fabsf(logit)));
    }
    __syncthreads();

    // Per-block loss -> global; last block reduces (deterministic order).
    __shared__ int s_is_last;
    if (tid == 0) {
        g_lossp[b] = (sloss[0] + sloss[1]) + (sloss[2] + sloss[3]);
        __threadfence();
        unsigned old = atomicAdd(&g_final_count, 1u);
        s_is_last = (old == NBLK - 1);
        if (s_is_last) g_final_count = 0;   // reset for next graph replay
    }
    __syncthreads();
    if (!s_is_last) return;

    __threadfence();
    __shared__ float sl[THREADS];
    sl[tid] = g_lossp[tid] + g_lossp[tid + THREADS];
    __syncthreads();
#pragma unroll
    for (int off = THREADS / 2; off > 0; off >>= 1) {
        if (tid < off) sl[tid] += sl[tid + off];
        __syncthreads();
    }
    if (tid == 0) out[2 * BATCH] = sl[0];
}

// ---------------------------------------------------------------------------
extern "C" void kernel_launch(void* const* d_in, const int* in_sizes, int n_in,
                              void* d_out, int out_size)
{
    const float* gate        = (const float*)d_in[0]; // [2048, 65536]
    const float* sparse_bias = (const float*)d_in[1]; // [65536]
    const float* global_bias = (const float*)d_in[2]; // [1]
    const float* label       = (const float*)d_in[3]; // [2048]
    float* out = (float*)d_out;                       // [4097]

    lr_kernel<<<NBLK, THREADS>>>(gate, sparse_bias, global_bias, label, out);
}

// round 16
// speedup vs baseline: 1.1720x; 1.0004x over previous
#include <cuda_runtime.h>
#include <math.h>

#define BATCH   2048
#define FID     65536
#define ROWS    4                   // rows per block (full columns)
#define NBLK    (BATCH / ROWS)      // 512 blocks
#define THREADS 256
#define NIT     (FID / (THREADS * 4))  // 64 column iterations

// Scratch (zero-initialized; counter self-resets each run for graph replay)
__device__ float        g_lossp[NBLK];
__device__ unsigned int g_final_count;

// ---------------------------------------------------------------------------
// Converged kernel (measured 80.4 / 81.9 / 82.0us across runs, ~83% DRAM):
// each block owns 4 complete rows (1 MB of gate) and emits logits/pred
// directly — no partials, no second launch. 4 independent LDG.128 per
// iteration at unroll 2 / regs 56 / occ 4 blocks is the measured optimum of
// the MLP-vs-occupancy curve (R11: fewer loads -> 98.8us; R14: more -> 94.2us).
// Loss via per-block fence+atomic; last block reduces 512 values in fixed
// order (deterministic). out layout: [logits(2048), pred(2048), loss(1)]
// ---------------------------------------------------------------------------
__global__ void __launch_bounds__(THREADS, 4) lr_kernel(
    const float* __restrict__ gate, const float* __restrict__ bias,
    const float* __restrict__ global_bias, const float* __restrict__ label,
    float* __restrict__ out)
{
    const int b    = blockIdx.x;
    const int tid  = threadIdx.x;
    const int warp = tid >> 5;
    const int lane = tid & 31;
    const size_t row0 = (size_t)b * ROWS;

    float s0 = 0.0f, s1 = 0.0f, s2 = 0.0f, s3 = 0.0f;

    const float* g0 = gate + row0 * FID;

#pragma unroll 2
    for (int it = 0; it < NIT; ++it) {
        const int col = it * (THREADS * 4) + tid * 4;
        const float4 bb = *reinterpret_cast<const float4*>(bias + col);
        float4 x0 = *reinterpret_cast<const float4*>(g0 + col);
        float4 x1 = *reinterpret_cast<const float4*>(g0 + FID + col);
        float4 x2 = *reinterpret_cast<const float4*>(g0 + 2 * FID + col);
        float4 x3 = *reinterpret_cast<const float4*>(g0 + 3 * FID + col);
        s0 += x0.x * bb.x + x0.y * bb.y + x0.z * bb.z + x0.w * bb.w;
        s1 += x1.x * bb.x + x1.y * bb.y + x1.z * bb.z + x1.w * bb.w;
        s2 += x2.x * bb.x + x2.y * bb.y + x2.z * bb.z + x2.w * bb.w;
        s3 += x3.x * bb.x + x3.y * bb.y + x3.z * bb.z + x3.w * bb.w;
    }

    // Block reduction: warp shfl per row-sum, then 8 warp values per row.
    float s[4] = {s0, s1, s2, s3};
    __shared__ float sm[ROWS][8];
#pragma unroll
    for (int r = 0; r < ROWS; ++r) {
        float v = s[r];
        v += __shfl_xor_sync(0xffffffffu, v, 16);
        v += __shfl_xor_sync(0xffffffffu, v, 8);
        v += __shfl_xor_sync(0xffffffffu, v, 4);
        v += __shfl_xor_sync(0xffffffffu, v, 2);
        v += __shfl_xor_sync(0xffffffffu, v, 1);
        if (lane == 0) sm[r][warp] = v;
    }
    __syncthreads();

    // Threads 0..3 finalize one row each: logit, pred, per-row loss.
    __shared__ float sloss[ROWS];
    if (tid < ROWS) {
        float t = 0.0f;
#pragma unroll
        for (int w = 0; w < 8; ++w) t += sm[tid][w];   // fixed order
        const int row = (int)row0 + tid;
        float logit = t + global_bias[0];
        out[row]         = logit;
        out[BATCH + row] = 1.0f / (1.0f + __expf(-logit));
        float y = label[row];
        sloss[tid] = fmaxf(logit, 0.0f) - logit * y + log1pf(expf(-fabsf(logit)));
    }
    __syncthreads();

    // Per-block loss -> global; last block reduces (deterministic order).
    __shared__ int s_is_last;
    if (tid == 0) {
        g_lossp[b] = (sloss[0] + sloss[1]) + (sloss[2] + sloss[3]);
        __threadfence();
        unsigned old = atomicAdd(&g_final_count, 1u);
        s_is_last = (old == NBLK - 1);
        if (s_is_last) g_final_count = 0;   // reset for next graph replay
    }
    __syncthreads();
    if (!s_is_last) return;

    __threadfence();
    __shared__ float sl[THREADS];
    sl[tid] = g_lossp[tid] + g_lossp[tid + THREADS];
    __syncthreads();
#pragma unroll
    for (int off = THREADS / 2; off > 0; off >>= 1) {
        if (tid < off) sl[tid] += sl[tid + off];
        __syncthreads();
    }
    if (tid == 0) out[2 * BATCH] = sl[0];
}

// ---------------------------------------------------------------------------
extern "C" void kernel_launch(void* const* d_in, const int* in_sizes, int n_in,
                              void* d_out, int out_size)
{
    const float* gate        = (const float*)d_in[0]; // [2048, 65536]
    const float* sparse_bias = (const float*)d_in[1]; // [65536]
    const float* global_bias = (const float*)d_in[2]; // [1]
    const float* label       = (const float*)d_in[3]; // [2048]
    float* out = (float*)d_out;                       // [4097]

    lr_kernel<<<NBLK, THREADS>>>(gate, sparse_bias, global_bias, label, out);
}